// round 15
// baseline (speedup 1.0000x reference)
#include <cuda_runtime.h>
#include <math.h>

// MultiHeadsAttModel: hyperbolic (Poincare-ball) multi-head attention.
// out = concat( out f32 [4,2000,32], att f32 [4,2000,5,5] )
// 2 kernels (R8 structure; inline-att fusion reverted -- it cost occupancy):
//   A) fused scan+phi (heterogeneous grid, scan at LTS cap, phi hidden under it)
//   B) att: 2 agents per warp, fully interleaved chains (ILP=2 on shuffle chains)

#define BB   4
#define NN   2000
#define KK   5
#define DD   32
#define M1   160
#define MINN 1e-15f
#define MAXN 0.996f    // (1 - 4e-3)/sqrt(c), c = 1

#define SCAN_T   256
#define SCAN_B8  8
#define TOT4     ((BB * NN * KK * NN) / 4)   // 20,000,000 uint4
#define SCAN_BLOCKS ((TOT4 + SCAN_T * SCAN_B8 - 1) / (SCAN_T * SCAN_B8))  // 9766

#define NNODE (BB * NN)                       // 8000
#define WPB   8                               // warps per phi block
#define PHI_BLOCKS (NNODE / WPB)              // 1000
#define SKST 161                              // padded kv row stride

#define A2       2                            // agents per att warp
#define WPB_ATT  4                            // warps per att block
#define ATT_BLOCKS (NNODE / (WPB_ATT * A2))   // 1000

__device__ int   g_nei[NNODE * KK];           // 40000 neighbor indices
__device__ float g_phi[NNODE * M1];           // 8000 x 160 node embeddings

__device__ __forceinline__ float artanhf_(float x) {
    const float lim = 1.0f - 1e-7f;
    x = fminf(fmaxf(x, -lim), lim);
    return 0.5f * (log1pf(x) - log1pf(-x));
}

__device__ __forceinline__ float wsum(float x) {
    #pragma unroll
    for (int o = 16; o > 0; o >>= 1) x += __shfl_xor_sync(0xffffffffu, x, o);
    return x;
}

// two independent reductions, interleaved -> 2x ILP on the shuffle chain
__device__ __forceinline__ void wsum2(float& x, float& y) {
    #pragma unroll
    for (int o = 16; o > 0; o >>= 1) {
        x += __shfl_xor_sync(0xffffffffu, x, o);
        y += __shfl_xor_sync(0xffffffffu, y, o);
    }
}

// ---------------- Kernel A: fused phi (blocks [0,1000)) + scan (rest) ----------------
__global__ void __launch_bounds__(SCAN_T)
scan_phi_kernel(const uint4* __restrict__ nei,
                const float* __restrict__ in_feats,
                const float* __restrict__ W1,
                const float* __restrict__ b1) {
    __shared__ float W1s[DD][M1 + 1];   // used by phi blocks only

    if (blockIdx.x >= PHI_BLOCKS) {
        // ================= scan role: streaming one-hot scan =================
        unsigned sb = blockIdx.x - PHI_BLOCKS;
        unsigned b0 = sb * (SCAN_T * SCAN_B8) + threadIdx.x;
        uint4 v[SCAN_B8];
        #pragma unroll
        for (int j = 0; j < SCAN_B8; j++) {
            unsigned i = b0 + j * SCAN_T;
            v[j] = (i < TOT4) ? __ldcs(nei + i) : make_uint4(0u, 0u, 0u, 0u);
        }
        #pragma unroll
        for (int j = 0; j < SCAN_B8; j++) {
            uint4 u = v[j];
            if ((u.x | u.y | u.z | u.w) != 0u) {
                unsigned i = b0 + j * SCAN_T;        // uint4 index; 2000 % 4 == 0
                unsigned r = i / 500u;               // flat row = bn*KK + k
                unsigned c4 = i * 4u - r * 2000u;
                unsigned c = c4 + (u.x ? 0u : (u.y ? 1u : (u.z ? 2u : 3u)));
                g_nei[r] = (int)c;
            }
        }
        return;
    }

    // ================= phi role: per-node embedding, warp-autonomous =================
    const int tid  = threadIdx.x;
    const int lane = tid & 31;
    const int warp = tid >> 5;
    for (int i = tid; i < M1 * DD; i += 32 * WPB) W1s[i & 31][i >> 5] = W1[i];
    __syncthreads();

    const int node = blockIdx.x * WPB + warp;      // < 8000

    // hb1 = proj(expmap0(b1)); lane owns rows lane+32j
    float b1v[5];
    float bsq = 0.f;
    #pragma unroll
    for (int j = 0; j < 5; j++) { b1v[j] = b1[lane + 32 * j]; bsq += b1v[j] * b1v[j]; }
    float bn2 = wsum(bsq);
    float hbn2;
    {
        float bnn = fmaxf(sqrtf(bn2), MINN);
        float e  = tanhf(bnn) / bnn;
        float pn = e * bnn;
        float pj = (pn > MAXN) ? MAXN / pn : 1.f;
        float f  = e * pj;
        hbn2 = f * f * bn2;
        #pragma unroll
        for (int j = 0; j < 5; j++) b1v[j] *= f;
    }

    // p = proj(expmap0(logmap0(x)))
    float x  = in_feats[node * DD + lane];
    float n2 = wsum(x * x);
    float ps, xnc;
    {
        float xn = fmaxf(sqrtf(n2), MINN);
        float f1 = artanhf_(xn) / xn;            // logmap0
        float fn = fmaxf(f1 * xn, MINN);
        float e  = tanhf(fn) / fn;               // expmap0
        float pn = e * fn;
        float pj = (pn > MAXN) ? MAXN / pn : 1.f;
        ps  = f1 * e * pj;
        xnc = fmaxf(pj * pn, MINN);
    }
    float p = ps * x;

    // mx = W1 @ p : lane owns rows lane+32j
    float mx[5] = {0.f, 0.f, 0.f, 0.f, 0.f};
    #pragma unroll
    for (int d = 0; d < DD; d++) {
        float pd = __shfl_sync(0xffffffffu, p, d);
        #pragma unroll
        for (int j = 0; j < 5; j++) mx[j] += W1s[d][lane + 32 * j] * pd;
    }

    float s1 = 0.f, s2 = 0.f;
    #pragma unroll
    for (int j = 0; j < 5; j++) { s1 += mx[j] * mx[j]; s2 += mx[j] * b1v[j]; }
    wsum2(s1, s2);
    float mxn2 = s1, mh = s2;

    float cA, cB;
    {
        float mxn  = fmaxf(sqrtf(mxn2), MINN);
        float rfac = (mxn2 == 0.f) ? 0.f
                   : tanhf(mxn / xnc * artanhf_(xnc)) / mxn;       // mobius_matvec
        float rn = rfac * mxn;
        float pj = (rn > MAXN) ? MAXN / fmaxf(rn, MINN) : 1.f;     // proj
        float g  = pj * rfac;
        float x2 = g * g * mxn2;
        float xy = g * mh;
        float y2 = hbn2;
        float A   = 1.f + 2.f * xy + y2;
        float Bc  = 1.f - x2;
        float den = fmaxf(1.f + 2.f * xy + x2 * y2, MINN);         // mobius_add
        cA = A * g / den;
        cB = Bc / den;
    }

    float cv[5];
    float c1 = 0.f, c2 = 0.f;
    #pragma unroll
    for (int j = 0; j < 5; j++) {
        cv[j] = cA * mx[j] + cB * b1v[j];
        float pp = fmaxf(cv[j], 0.f);
        c1 += cv[j] * cv[j];
        c2 += pp * pp;
    }
    wsum2(c1, c2);
    float cn2 = c1, pos2 = c2;
    float ql;
    {
        float cn = fmaxf(sqrtf(cn2), MINN);
        float pj = (cn > MAXN) ? MAXN / cn : 1.f;
        float nn = fmaxf(pj * cn, MINN);
        float l  = pj * artanhf_(nn) / nn;         // logmap0(proj(res)); l >= 0
        float nx = fmaxf(l * sqrtf(pos2), MINN);   // ||relu(l*cv)||
        float ef = tanhf(nx) / nx;
        float en = ef * nx;
        float pj2 = (en > MAXN) ? MAXN / en : 1.f;
        float fn = fmaxf(pj2 * en, MINN);
        ql = artanhf_(fn) / fn * pj2 * ef * l;
    }
    #pragma unroll
    for (int j = 0; j < 5; j++)
        g_phi[node * M1 + lane + 32 * j] = ql * fmaxf(cv[j], 0.f);
}

// ---------------- Kernel B: attention + layer 2, 2 agents per warp ----------------
__global__ void __launch_bounds__(32 * WPB_ATT)
att_kernel(const float* __restrict__ W2,
           const float* __restrict__ b2,
           float* __restrict__ out,
           float* __restrict__ att_out) {
    __shared__ float W2s[DD][DD + 1];
    __shared__ float skv[WPB_ATT][A2][6][SKST];
    __shared__ float satt[WPB_ATT][A2][32];

    const int tid  = threadIdx.x;
    const int lane = tid & 31;
    const int warp = tid >> 5;
    for (int i = tid; i < DD * DD; i += 32 * WPB_ATT) W2s[i & 31][i >> 5] = W2[i];
    __syncthreads();

    const int bn0 = (blockIdx.x * WPB_ATT + warp) * A2;   // < 8000

    // gather q + kv for both agents (independent loads, deep MLP)
    #pragma unroll
    for (int a = 0; a < A2; a++) {
        int bn = bn0 + a;
        int b  = bn / NN;
        #pragma unroll
        for (int v = 0; v < 6; v++) {
            int row = (v == 0) ? bn : b * NN + g_nei[bn * KK + v - 1];
            #pragma unroll
            for (int j = 0; j < 5; j++)
                skv[warp][a][v][lane + 32 * j] = g_phi[row * M1 + lane + 32 * j];
        }
    }
    __syncwarp();

    // logits: lane < 25 -> (hd = lane/5, k = lane%5), both agents interleaved
    if (lane < 25) {
        int hd = lane / 5, k = lane - hd * 5;
        float l0 = 0.f, l1 = 0.f;
        #pragma unroll 8
        for (int d = 0; d < DD; d++) {
            l0 += skv[warp][0][0][d * 5 + hd] * skv[warp][0][k + 1][d * 5 + hd];
            l1 += skv[warp][1][0][d * 5 + hd] * skv[warp][1][k + 1][d * 5 + hd];
        }
        satt[warp][0][lane] = l0;
        satt[warp][1][lane] = l1;
    }
    __syncwarp();
    if (lane < 5) {
        #pragma unroll
        for (int a = 0; a < A2; a++) {
            float m = -1e30f;
            #pragma unroll
            for (int k = 0; k < 5; k++) m = fmaxf(m, satt[warp][a][lane * 5 + k]);
            float e[5], s = 0.f;
            #pragma unroll
            for (int k = 0; k < 5; k++) { e[k] = expf(satt[warp][a][lane * 5 + k] - m); s += e[k]; }
            float inv = 1.f / s;
            #pragma unroll
            for (int k = 0; k < 5; k++) {
                float av = e[k] * inv;
                satt[warp][a][lane * 5 + k] = av;
                if (att_out) att_out[(size_t)(bn0 + a) * 25 + lane * 5 + k] = av;
            }
        }
    }
    __syncwarp();

    // head-mean output (lane = output dim d), both agents
    float o[A2];
    #pragma unroll
    for (int a = 0; a < A2; a++) {
        float acc = 0.f;
        #pragma unroll
        for (int hd = 0; hd < 5; hd++) {
            #pragma unroll
            for (int k = 0; k < 5; k++)
                acc += satt[warp][a][hd * 5 + k] * skv[warp][a][k + 1][lane * 5 + hd];
        }
        o[a] = acc * 0.2f;
    }

    // hb2 = proj(expmap0(b2)) -- agent-independent, once per warp
    float bt2 = b2[lane];
    float hbv, hbn22;
    {
        float n2b = wsum(bt2 * bt2);
        float bnn = fmaxf(sqrtf(n2b), MINN);
        float e  = tanhf(bnn) / bnn;
        float pn = e * bnn;
        float pj = (pn > MAXN) ? MAXN / pn : 1.f;
        float f  = e * pj;
        hbv = bt2 * f;
        hbn22 = f * f * n2b;
    }

    // ---- layer 2, fully paired across the two agents ----
    float n2[A2] = {o[0] * o[0], o[1] * o[1]};
    wsum2(n2[0], n2[1]);
    float p[A2], p2n[A2];
    #pragma unroll
    for (int a = 0; a < A2; a++) {
        float xn = fmaxf(sqrtf(n2[a]), MINN);
        float e  = tanhf(xn) / xn;
        float pn = e * xn;
        float pj = (pn > MAXN) ? MAXN / pn : 1.f;
        p[a]   = e * pj * o[a];                 // proj(expmap0(out32))
        p2n[a] = fmaxf(pj * pn, MINN);
    }
    float m[A2] = {0.f, 0.f};
    #pragma unroll
    for (int dd = 0; dd < DD; dd++) {
        float w = W2s[dd][lane];
        float pd0 = __shfl_sync(0xffffffffu, p[0], dd);
        float pd1 = __shfl_sync(0xffffffffu, p[1], dd);
        m[0] += w * pd0;
        m[1] += w * pd1;
    }
    float mxn2[A2] = {m[0] * m[0], m[1] * m[1]};
    float mh[A2]   = {m[0] * hbv, m[1] * hbv};
    wsum2(mxn2[0], mxn2[1]);
    wsum2(mh[0], mh[1]);
    float c_[A2];
    #pragma unroll
    for (int a = 0; a < A2; a++) {
        float mxn  = fmaxf(sqrtf(mxn2[a]), MINN);
        float rfac = (mxn2[a] == 0.f) ? 0.f
                   : tanhf(mxn / p2n[a] * artanhf_(p2n[a])) / mxn;
        float rn  = rfac * mxn;
        float pjr = (rn > MAXN) ? MAXN / fmaxf(rn, MINN) : 1.f;
        float g   = pjr * rfac;
        float x2  = g * g * mxn2[a];
        float xy  = g * mh[a];
        float y2  = hbn22;
        float A   = 1.f + 2.f * xy + y2;
        float Bc  = 1.f - x2;
        float den = fmaxf(1.f + 2.f * xy + x2 * y2, MINN);
        c_[a] = (A * g * m[a] + Bc * hbv) / den;
    }
    float cn2[A2] = {c_[0] * c_[0], c_[1] * c_[1]};
    wsum2(cn2[0], cn2[1]);
    float xtv[A2];
    #pragma unroll
    for (int a = 0; a < A2; a++) {
        float cn  = fmaxf(sqrtf(cn2[a]), MINN);
        float pj2 = (cn > MAXN) ? MAXN / cn : 1.f;
        float nnc = fmaxf(pj2 * cn, MINN);
        float u   = artanhf_(nnc) / nnc * pj2 * c_[a];
        xtv[a] = fmaxf(u, 0.f);
    }
    float xn2[A2] = {xtv[0] * xtv[0], xtv[1] * xtv[1]};
    wsum2(xn2[0], xn2[1]);
    #pragma unroll
    for (int a = 0; a < A2; a++) {
        float nx  = fmaxf(sqrtf(xn2[a]), MINN);
        float ef  = tanhf(nx) / nx;
        float en  = ef * nx;
        float pj3 = (en > MAXN) ? MAXN / en : 1.f;
        out[(size_t)(bn0 + a) * DD + lane] = pj3 * ef * xtv[a];
    }
}

extern "C" void kernel_launch(void* const* d_in, const int* in_sizes, int n_in,
                              void* d_out, int out_size) {
    const float* in_feats = (const float*)d_in[0];
    const float* in_nei   = (const float*)d_in[1];
    const float* W1       = (const float*)d_in[2];
    const float* b1       = (const float*)d_in[3];
    const float* W2       = (const float*)d_in[4];
    const float* b2       = (const float*)d_in[5];
    float* out = (float*)d_out;
    const int out_elems = BB * NN * DD;                 // 256000
    const int att_elems = BB * NN * 25;                 // 200000
    float* att = (out_size >= out_elems + att_elems) ? out + out_elems : nullptr;

    scan_phi_kernel<<<PHI_BLOCKS + SCAN_BLOCKS, SCAN_T>>>(
        (const uint4*)in_nei, in_feats, W1, b1);
    att_kernel<<<ATT_BLOCKS, 32 * WPB_ATT>>>(W2, b2, out, att);
}